// round 1
// baseline (speedup 1.0000x reference)
#include <cuda_runtime.h>
#include <cstdint>
#include <cstddef>

#define DEPTH 18
#define NNODES ((1 << DEPTH) - 1)      // 262143
#define HDIM 128
#define LEAF_N (1 << (DEPTH - 1))      // 131072

// ---------------- device scratch (no cudaMalloc allowed) ----------------
__device__ float g_h[(size_t)NNODES * HDIM];        // 134 MB
__device__ float g_c[(size_t)NNODES * HDIM];        // 134 MB
__device__ float g_iou[(size_t)LEAF_N * 384];       // 201 MB (per-level iou scratch)
__device__ float g_fprod[(size_t)LEAF_N * HDIM];    // 67 MB  (per-child f*c scratch)

__device__ __forceinline__ float sigmf(float x) {
    return 1.0f / (1.0f + __expf(-x));
}

// ---------------- fused level GEMM ----------------
// mode 0: leaves:    out_iou[m, 0:384] = emb(node m) @ W_iou           (K=128)
// mode 1: internal:  out_iou[m, 0:384] = emb(m) @ W_iou + (h_l+h_r) @ U_iou  (K=256)
// mode 2: f-gate:    fprod[ch, 0:128]  = sigmoid(emb(parent)@W_f + h_ch@U_f + b_f) * c_ch
// Tiling: BM=BN=128, BK=16, 256 threads, 8x8 register blocking.
constexpr int BM = 128, BN = 128, BK = 16;

__global__ __launch_bounds__(256, 2)
void tree_gemm(int mode,
               const int* __restrict__ xids, const int* __restrict__ msk,
               const float* __restrict__ emb,
               const float* __restrict__ Wa, const float* __restrict__ Wb,
               const float* __restrict__ bias, int Ncols,
               int s0, int nP)
{
    const int M = (mode == 2) ? 2 * nP : nP;
    const int K = (mode == 0) ? 128 : 256;
    const int s1 = 2 * s0 + 1;
    const int m0 = blockIdx.x * BM;
    const int n0 = blockIdx.y * BN;

    __shared__ float As[BK][BM];
    __shared__ float Bs[BK][BN];
    __shared__ const float* rEmb[BM];
    __shared__ const float* rH0[BM];
    __shared__ const float* rH1[BM];

    const int tid = threadIdx.x;

    if (tid < BM) {
        int gm = m0 + tid;
        if (gm < M) {
            int node, chld0 = -1, chld1 = -1;
            if (mode == 2) {
                node  = s0 + (gm >> 1);
                chld0 = s1 + gm;
            } else {
                node = s0 + gm;
                if (mode == 1) { chld0 = s1 + 2 * gm; chld1 = chld0 + 1; }
            }
            int gid = xids[node] * msk[node];
            rEmb[tid] = emb + (size_t)gid * HDIM;
            rH0[tid]  = (chld0 >= 0) ? g_h + (size_t)chld0 * HDIM : nullptr;
            rH1[tid]  = (chld1 >= 0) ? g_h + (size_t)chld1 * HDIM : nullptr;
        } else {
            rEmb[tid] = nullptr; rH0[tid] = nullptr; rH1[tid] = nullptr;
        }
    }
    __syncthreads();

    float acc[8][8];
    #pragma unroll
    for (int i = 0; i < 8; i++)
        #pragma unroll
        for (int j = 0; j < 8; j++) acc[i][j] = 0.f;

    const int ty = tid >> 4;   // 0..15
    const int tx = tid & 15;   // 0..15

    for (int k0 = 0; k0 < K; k0 += BK) {
        // ---- load A tile (BM x BK), 2 float4 per thread ----
        {
            const int r  = tid >> 2;          // 0..63
            const int kk = (tid & 3) * 4;     // 0,4,8,12
            const int gk = k0 + kk;
            #pragma unroll
            for (int half = 0; half < 2; half++) {
                const int rr = r + half * 64;
                float4 v = make_float4(0.f, 0.f, 0.f, 0.f);
                if (gk < 128) {
                    const float* p = rEmb[rr];
                    if (p) v = *(const float4*)(p + gk);
                } else {
                    const float* p = rH0[rr];
                    if (p) {
                        v = *(const float4*)(p + gk - 128);
                        const float* q = rH1[rr];
                        if (q) {
                            float4 w = *(const float4*)(q + gk - 128);
                            v.x += w.x; v.y += w.y; v.z += w.z; v.w += w.w;
                        }
                    }
                }
                As[kk + 0][rr] = v.x; As[kk + 1][rr] = v.y;
                As[kk + 2][rr] = v.z; As[kk + 3][rr] = v.w;
            }
        }
        // ---- load B tile (BK x BN), coalesced float4 ----
        {
            const int kb  = tid >> 5;           // 0..7
            const int col = (tid & 31) * 4;     // 0..124
            #pragma unroll
            for (int half = 0; half < 2; half++) {
                const int kr = kb + half * 8;
                const int gk = k0 + kr;
                const float* src = (gk < 128) ? (Wa + (size_t)gk * Ncols)
                                              : (Wb + (size_t)(gk - 128) * Ncols);
                *(float4*)&Bs[kr][col] = *(const float4*)(src + n0 + col);
            }
        }
        __syncthreads();

        #pragma unroll
        for (int k = 0; k < BK; k++) {
            float4 a0 = *(const float4*)&As[k][ty * 8];
            float4 a1 = *(const float4*)&As[k][ty * 8 + 4];
            float4 b0 = *(const float4*)&Bs[k][tx * 8];
            float4 b1 = *(const float4*)&Bs[k][tx * 8 + 4];
            float av[8] = {a0.x, a0.y, a0.z, a0.w, a1.x, a1.y, a1.z, a1.w};
            float bv[8] = {b0.x, b0.y, b0.z, b0.w, b1.x, b1.y, b1.z, b1.w};
            #pragma unroll
            for (int i = 0; i < 8; i++)
                #pragma unroll
                for (int j = 0; j < 8; j++)
                    acc[i][j] += av[i] * bv[j];
        }
        __syncthreads();
    }

    // ---- epilogue ----
    #pragma unroll
    for (int i = 0; i < 8; i++) {
        const int gm = m0 + ty * 8 + i;
        if (gm >= M) continue;
        #pragma unroll
        for (int j = 0; j < 8; j += 4) {
            const int col = n0 + tx * 8 + j;
            float4 v;
            v.x = acc[i][j + 0] + bias[col + 0];
            v.y = acc[i][j + 1] + bias[col + 1];
            v.z = acc[i][j + 2] + bias[col + 2];
            v.w = acc[i][j + 3] + bias[col + 3];
            if (mode == 2) {
                const float4 cc = *(const float4*)(g_c + (size_t)(s1 + gm) * HDIM + col);
                v.x = sigmf(v.x) * cc.x;
                v.y = sigmf(v.y) * cc.y;
                v.z = sigmf(v.z) * cc.z;
                v.w = sigmf(v.w) * cc.w;
                *(float4*)&g_fprod[(size_t)gm * HDIM + col] = v;
            } else {
                *(float4*)&g_iou[(size_t)gm * 384 + col] = v;
            }
        }
    }
}

// ---------------- elementwise gate update ----------------
__global__ void node_update(int s0, int n, int internal)
{
    const int idx = blockIdx.x * blockDim.x + threadIdx.x;
    if (idx >= n * HDIM) return;
    const int m = idx >> 7;
    const int j = idx & 127;

    const float i_ = g_iou[(size_t)m * 384 + j];
    const float o_ = g_iou[(size_t)m * 384 + 128 + j];
    const float u_ = g_iou[(size_t)m * 384 + 256 + j];

    float fc = 0.f;
    if (internal)
        fc = g_fprod[(size_t)(2 * m) * HDIM + j] + g_fprod[(size_t)(2 * m + 1) * HDIM + j];

    const float c = sigmf(i_) * tanhf(u_) + fc;
    const float h = sigmf(o_) * tanhf(c);
    g_c[(size_t)(s0 + m) * HDIM + j] = c;
    g_h[(size_t)(s0 + m) * HDIM + j] = h;
}

// ---------------- output projection: warp per node ----------------
__global__ void out_gemm(const float* __restrict__ Wout,
                         const float* __restrict__ bout,
                         float* __restrict__ out)
{
    __shared__ float Ws[HDIM * 5];
    __shared__ float bs[5];
    const int tid = threadIdx.x;
    for (int i = tid; i < HDIM * 5; i += blockDim.x) Ws[i] = Wout[i];
    if (tid < 5) bs[tid] = bout[tid];
    __syncthreads();

    const int node = (blockIdx.x * blockDim.x + tid) >> 5;
    const int lane = tid & 31;
    if (node >= NNODES) return;

    const float* hp = g_h + (size_t)node * HDIM;
    float p[5] = {0.f, 0.f, 0.f, 0.f, 0.f};
    #pragma unroll
    for (int e = 0; e < 4; e++) {
        const int k = e * 32 + lane;
        const float x = hp[k];
        #pragma unroll
        for (int c = 0; c < 5; c++) p[c] += x * Ws[k * 5 + c];
    }
    #pragma unroll
    for (int off = 16; off > 0; off >>= 1)
        #pragma unroll
        for (int c = 0; c < 5; c++)
            p[c] += __shfl_xor_sync(0xffffffffu, p[c], off);

    if (lane == 0) {
        #pragma unroll
        for (int c = 0; c < 5; c++)
            out[(size_t)node * 5 + c] = p[c] + bs[c];
    }
}

// ---------------- launch ----------------
extern "C" void kernel_launch(void* const* d_in, const int* in_sizes, int n_in,
                              void* d_out, int out_size)
{
    const int*   x_ids = (const int*)d_in[0];
    const int*   mask  = (const int*)d_in[1];
    const float* emb   = (const float*)d_in[2];
    const float* W_iou = (const float*)d_in[3];
    const float* U_iou = (const float*)d_in[4];
    const float* b_iou = (const float*)d_in[5];
    const float* W_f   = (const float*)d_in[6];
    const float* U_f   = (const float*)d_in[7];
    const float* b_f   = (const float*)d_in[8];
    const float* W_out = (const float*)d_in[9];
    const float* b_out = (const float*)d_in[10];
    float* out = (float*)d_out;

    for (int d = DEPTH - 1; d >= 0; --d) {
        const int s0 = (1 << d) - 1;
        const int n  = 1 << d;

        if (d == DEPTH - 1) {
            // leaves: iou = emb @ W_iou + b_iou
            dim3 grid((n + BM - 1) / BM, 3);
            tree_gemm<<<grid, 256>>>(0, x_ids, mask, emb, W_iou, nullptr, b_iou, 384, s0, n);
            const int total = n * HDIM;
            node_update<<<(total + 255) / 256, 256>>>(s0, n, 0);
        } else {
            // iou = emb @ W_iou + (h_l + h_r) @ U_iou + b_iou
            dim3 grid1((n + BM - 1) / BM, 3);
            tree_gemm<<<grid1, 256>>>(1, x_ids, mask, emb, W_iou, U_iou, b_iou, 384, s0, n);
            // fprod[ch] = sigmoid(emb(parent) @ W_f + h_ch @ U_f + b_f) * c_ch
            dim3 grid2((2 * n + BM - 1) / BM, 1);
            tree_gemm<<<grid2, 256>>>(2, x_ids, mask, emb, W_f, U_f, b_f, 128, s0, n);
            const int total = n * HDIM;
            node_update<<<(total + 255) / 256, 256>>>(s0, n, 1);
        }
    }

    // out = h_all @ W_out + b_out
    const int warps_per_block = 8;
    const int blocks = (NNODES + warps_per_block - 1) / warps_per_block;
    out_gemm<<<blocks, warps_per_block * 32>>>(W_out, b_out, out);
}

// round 8
// speedup vs baseline: 1.8215x; 1.8215x over previous
#include <cuda_runtime.h>
#include <cuda_bf16.h>
#include <mma.h>
#include <cstdint>
#include <cstddef>

using namespace nvcuda;

#define DEPTH 18
#define NNODES ((1 << DEPTH) - 1)      // 262143
#define HDIM 128
#define LEAF_N (1 << (DEPTH - 1))      // 131072
#define HALF_LEAF (LEAF_N / 2)         // 65536

// ================= device scratch (416 MiB total; largest object 128 MiB) =====
__device__ __align__(128) float g_h[(size_t)NNODES * HDIM];          // 128 MiB
__device__ __align__(128) float g_c[(size_t)NNODES * HDIM];          // 128 MiB
__device__ __align__(128) float g_fraw[(size_t)LEAF_N * HDIM];       // 64 MiB: raw fgate pre-act
__device__ __align__(128) float g_iouraw[(size_t)HALF_LEAF * 384];   // 96 MiB: raw iou pre-act
// weight images, bf16 pairs packed in uint32: [tile][n(128)][kpair(128)] (K=256)
// tiles 0-2: [W_iou;U_iou] n-tiles, tile 3: [W_f;U_f]
__device__ __align__(128) uint32_t g_Bhi[4 * 128 * 128];
__device__ __align__(128) uint32_t g_Blo[4 * 128 * 128];

__device__ __forceinline__ float sigmf(float x) { return 1.0f / (1.0f + __expf(-x)); }

// pure-integer bf16 hi/lo split (truncation): hi = top16(f), lo = top16(f - hi)
__device__ __forceinline__ void split2(float f0, float f1, uint32_t& hiw, uint32_t& low) {
    const uint32_t h0 = __float_as_uint(f0) & 0xFFFF0000u;
    const uint32_t h1 = __float_as_uint(f1) & 0xFFFF0000u;
    const uint32_t l0 = __float_as_uint(f0 - __uint_as_float(h0)) & 0xFFFF0000u;
    const uint32_t l1 = __float_as_uint(f1 - __uint_as_float(h1)) & 0xFFFF0000u;
    hiw = (h0 >> 16) | h1;
    low = (l0 >> 16) | l1;
}

// ================= static smem layout (bf16 elems, 40-elem padded rows) =====
#define PADK 40
#define E_ALO 5120
#define E_BHI 10240
#define E_BLO 15360
#define SM_ELEMS 20480            // 40 KB

// ================= one-time weight prep =================
// g_B*[t][n][kp]: K rows 0..255 = [W(0..127); U(128..255)], column n (output dim)
__global__ void prep_weights(const float* __restrict__ Wiou, const float* __restrict__ Wf,
                             const float* __restrict__ Uiou, const float* __restrict__ Uf)
{
    const int idx = blockIdx.x * blockDim.x + threadIdx.x;
    if (idx >= 4 * 128 * 128) return;
    const int t = idx >> 14;
    const int n = (idx >> 7) & 127;
    const int kp = idx & 127;
    float v[2];
    #pragma unroll
    for (int e = 0; e < 2; e++) {
        const int k = kp * 2 + e;
        if (t < 3) {
            const int nn = t * 128 + n;
            v[e] = (k < 128) ? Wiou[k * 384 + nn] : Uiou[(k - 128) * 384 + nn];
        } else {
            v[e] = (k < 128) ? Wf[k * 128 + n] : Uf[(k - 128) * 128 + n];
        }
    }
    uint32_t hiw, low;
    split2(v[0], v[1], hiw, low);
    g_Bhi[idx] = hiw;
    g_Blo[idx] = low;
}

// ================= wmma GEMM core =================
// CTA = 128 rows x 128 cols, 8 warps (wm 0..3 = 32 rows, wn 0..1 = 64 cols).
// K chunked by 32; chunk kc<4 sources pe (emb row), kc>=4 sources ph0(+ph1 summed).
// 3 bf16-split products (hi*hi + hi*lo + lo*hi), fp32 accum. Stores raw (no bias).
__device__ __forceinline__ void gemm_core(
    __nv_bfloat16* sm, int tid,
    const float* pe, const float* ph0, const float* ph1,   // per-thread row ptrs (nullable)
    int nkc,
    const uint32_t* bhi, const uint32_t* blo,              // weight tile base (128n x 128kp)
    float* __restrict__ C, int ldC, int m0, int colbase)
{
    const int wid = tid >> 5;
    const int wm = wid >> 1;
    const int wn = wid & 1;
    const int r = tid >> 1;
    const int sel = tid & 1;

    wmma::fragment<wmma::accumulator, 16, 16, 16, float> acc[2][4];
    #pragma unroll
    for (int mt = 0; mt < 2; mt++)
        #pragma unroll
        for (int nt = 0; nt < 4; nt++)
            wmma::fill_fragment(acc[mt][nt], 0.0f);

    for (int kc = 0; kc < nkc; kc++) {
        if (kc) __syncthreads();
        // ---- stage A chunk (2 threads per row, 16 floats each) ----
        {
            const float* p0;
            const float* p1 = nullptr;
            if (kc < 4) {
                p0 = pe ? pe + kc * 32 + sel * 16 : nullptr;
            } else {
                p0 = ph0 ? ph0 + (kc - 4) * 32 + sel * 16 : nullptr;
                p1 = ph1 ? ph1 + (kc - 4) * 32 + sel * 16 : nullptr;
            }
            uint32_t* dhi = (uint32_t*)(sm + r * PADK) + sel * 8;
            uint32_t* dlo = (uint32_t*)(sm + E_ALO + r * PADK) + sel * 8;
            if (p0) {
                #pragma unroll
                for (int q = 0; q < 4; q++) {
                    float4 f = *(const float4*)(p0 + 4 * q);
                    if (p1) {
                        const float4 g = *(const float4*)(p1 + 4 * q);
                        f.x += g.x; f.y += g.y; f.z += g.z; f.w += g.w;
                    }
                    uint32_t h0, l0, h1, l1;
                    split2(f.x, f.y, h0, l0);
                    split2(f.z, f.w, h1, l1);
                    dhi[2 * q] = h0; dhi[2 * q + 1] = h1;
                    dlo[2 * q] = l0; dlo[2 * q + 1] = l1;
                }
            } else {
                #pragma unroll
                for (int q = 0; q < 8; q++) { dhi[q] = 0u; dlo[q] = 0u; }
            }
        }
        // ---- stage B chunk: 128 n-rows x 32 k (4 uint4/row; row = 32 uint4) ----
        {
            const uint4* shi = (const uint4*)bhi + kc * 4;
            const uint4* slo = (const uint4*)blo + kc * 4;
            #pragma unroll
            for (int i = tid; i < 512; i += 256) {
                const int nn = i >> 2;
                const int q = i & 3;
                *(uint4*)(sm + E_BHI + nn * PADK + q * 8) = shi[nn * 32 + q];
                *(uint4*)(sm + E_BLO + nn * PADK + q * 8) = slo[nn * 32 + q];
            }
        }
        __syncthreads();

        #pragma unroll
        for (int p = 0; p < 3; p++) {
            const int aBase = (p == 2) ? E_ALO : 0;
            const int bBase = (p == 1) ? E_BLO : E_BHI;
            #pragma unroll
            for (int ks = 0; ks < 2; ks++) {
                wmma::fragment<wmma::matrix_a, 16, 16, 16, __nv_bfloat16, wmma::row_major> a[2];
                #pragma unroll
                for (int mt = 0; mt < 2; mt++)
                    wmma::load_matrix_sync(a[mt],
                        sm + aBase + (wm * 32 + mt * 16) * PADK + ks * 16, PADK);
                #pragma unroll
                for (int nt = 0; nt < 4; nt++) {
                    wmma::fragment<wmma::matrix_b, 16, 16, 16, __nv_bfloat16, wmma::col_major> b;
                    wmma::load_matrix_sync(b,
                        sm + bBase + (wn * 64 + nt * 16) * PADK + ks * 16, PADK);
                    #pragma unroll
                    for (int mt = 0; mt < 2; mt++)
                        wmma::mma_sync(acc[mt][nt], a[mt], b, acc[mt][nt]);
                }
            }
        }
    }

    #pragma unroll
    for (int mt = 0; mt < 2; mt++)
        #pragma unroll
        for (int nt = 0; nt < 4; nt++) {
            const int row0 = m0 + wm * 32 + mt * 16;
            const int col0 = colbase + wn * 64 + nt * 16;
            wmma::store_matrix_sync(C + (size_t)row0 * ldC + col0, acc[mt][nt],
                                    ldC, wmma::mem_row_major);
        }
}

// leaves (half at a time): g_iouraw[m] = emb(leaf off+m) @ W_iou (K=128); grid (3, 512)
__global__ __launch_bounds__(256)
void leaf_gemm(const int* __restrict__ xids, const int* __restrict__ msk,
               const float* __restrict__ emb, int off)
{
    __shared__ __align__(16) __nv_bfloat16 sm[SM_ELEMS];
    const int tid = threadIdx.x;
    const int bt = blockIdx.x;
    const int m0 = blockIdx.y * 128;

    const int node = (LEAF_N - 1) + off + m0 + (tid >> 1);
    const int gid = xids[node] * msk[node];
    const float* pe = emb + (size_t)gid * HDIM;

    gemm_core(sm, tid, pe, nullptr, nullptr, 4,
              g_Bhi + bt * 16384, g_Blo + bt * 16384,
              g_iouraw, 384, m0, bt * 128);
}

// internal level: bx 0..2 = iou n-tiles (A=[emb(node)|h_l+h_r], K=256),
//                 bx 3    = fgate      (A=[emb(parent)|h_child], K=256)
__global__ __launch_bounds__(256)
void level_gemm(const int* __restrict__ xids, const int* __restrict__ msk,
                const float* __restrict__ emb, int s0, int n)
{
    __shared__ __align__(16) __nv_bfloat16 sm[SM_ELEMS];
    const int tid = threadIdx.x;
    const int bx = blockIdx.x;
    const int m0 = blockIdx.y * 128;
    const int s1 = 2 * s0 + 1;
    const int r = tid >> 1;

    const float* pe = nullptr;
    const float* ph0 = nullptr;
    const float* ph1 = nullptr;

    if (bx < 3) {
        if (m0 >= n) return;
        const int m = m0 + r;
        if (m < n) {
            const int node = s0 + m;
            const int gid = xids[node] * msk[node];
            pe  = emb + (size_t)gid * HDIM;
            ph0 = g_h + (size_t)(s1 + 2 * m) * HDIM;
            ph1 = g_h + (size_t)(s1 + 2 * m + 1) * HDIM;
        }
        gemm_core(sm, tid, pe, ph0, ph1, 8,
                  g_Bhi + bx * 16384, g_Blo + bx * 16384,
                  g_iouraw, 384, m0, bx * 128);
    } else {
        const int ch = m0 + r;
        if (ch < 2 * n) {
            const int parent = s0 + (ch >> 1);
            const int gid = xids[parent] * msk[parent];
            pe  = emb + (size_t)gid * HDIM;
            ph0 = g_h + (size_t)(s1 + ch) * HDIM;
        }
        gemm_core(sm, tid, pe, ph0, nullptr, 8,
                  g_Bhi + 3 * 16384, g_Blo + 3 * 16384,
                  g_fraw, 128, m0, 0);
    }
}

// ================= elementwise (biases folded here) =================
__global__ void leaf_update(int off, const float* __restrict__ biou)
{
    const int idx = blockIdx.x * blockDim.x + threadIdx.x;
    if (idx >= HALF_LEAF * HDIM) return;
    const int m = idx >> 7;
    const int j = idx & 127;
    const int node = (LEAF_N - 1) + off + m;
    const float iv = g_iouraw[(size_t)m * 384 + j]       + biou[j];
    const float ov = g_iouraw[(size_t)m * 384 + 128 + j] + biou[128 + j];
    const float uv = g_iouraw[(size_t)m * 384 + 256 + j] + biou[256 + j];
    const float cv = sigmf(iv) * tanhf(uv);
    const float hv = sigmf(ov) * tanhf(cv);
    g_c[(size_t)node * HDIM + j] = cv;
    g_h[(size_t)node * HDIM + j] = hv;
}

__global__ void level_update(int s0, int n,
                             const float* __restrict__ biou, const float* __restrict__ bfv)
{
    const int idx = blockIdx.x * blockDim.x + threadIdx.x;
    if (idx >= n * HDIM) return;
    const int m = idx >> 7;
    const int j = idx & 127;
    const int node = s0 + m;
    const float bf = bfv[j];
    const float c0 = g_c[(size_t)(2 * node + 1) * HDIM + j];
    const float c1 = g_c[(size_t)(2 * node + 2) * HDIM + j];
    const float f0 = sigmf(g_fraw[(size_t)(2 * m) * HDIM + j] + bf);
    const float f1 = sigmf(g_fraw[(size_t)(2 * m + 1) * HDIM + j] + bf);
    const float fc = f0 * c0 + f1 * c1;
    const float iv = g_iouraw[(size_t)m * 384 + j]       + biou[j];
    const float ov = g_iouraw[(size_t)m * 384 + 128 + j] + biou[128 + j];
    const float uv = g_iouraw[(size_t)m * 384 + 256 + j] + biou[256 + j];
    const float cv = sigmf(iv) * tanhf(uv) + fc;
    const float hv = sigmf(ov) * tanhf(cv);
    g_c[(size_t)node * HDIM + j] = cv;
    g_h[(size_t)node * HDIM + j] = hv;
}

// ================= output projection (proven in R1) =================
__global__ void out_gemm(const float* __restrict__ Wout,
                         const float* __restrict__ bout,
                         float* __restrict__ out)
{
    __shared__ float Ws[HDIM * 5];
    __shared__ float bs[5];
    const int tid = threadIdx.x;
    for (int i = tid; i < HDIM * 5; i += blockDim.x) Ws[i] = Wout[i];
    if (tid < 5) bs[tid] = bout[tid];
    __syncthreads();

    const int node = (blockIdx.x * blockDim.x + tid) >> 5;
    const int lane = tid & 31;
    if (node >= NNODES) return;

    const float* hp = g_h + (size_t)node * HDIM;
    float p[5] = {0.f, 0.f, 0.f, 0.f, 0.f};
    #pragma unroll
    for (int e = 0; e < 4; e++) {
        const int k = e * 32 + lane;
        const float x = hp[k];
        #pragma unroll
        for (int c = 0; c < 5; c++) p[c] += x * Ws[k * 5 + c];
    }
    #pragma unroll
    for (int off = 16; off > 0; off >>= 1)
        #pragma unroll
        for (int c = 0; c < 5; c++)
            p[c] += __shfl_xor_sync(0xffffffffu, p[c], off);

    if (lane == 0) {
        #pragma unroll
        for (int c = 0; c < 5; c++)
            out[(size_t)node * 5 + c] = p[c] + bs[c];
    }
}

// ================= launch =================
extern "C" void kernel_launch(void* const* d_in, const int* in_sizes, int n_in,
                              void* d_out, int out_size)
{
    const int*   x_ids = (const int*)d_in[0];
    const int*   mask  = (const int*)d_in[1];
    const float* emb   = (const float*)d_in[2];
    const float* W_iou = (const float*)d_in[3];
    const float* U_iou = (const float*)d_in[4];
    const float* b_iou = (const float*)d_in[5];
    const float* W_f   = (const float*)d_in[6];
    const float* U_f   = (const float*)d_in[7];
    const float* b_f   = (const float*)d_in[8];
    const float* W_out = (const float*)d_in[9];
    const float* b_out = (const float*)d_in[10];
    float* out = (float*)d_out;

    prep_weights<<<(4 * 128 * 128 + 255) / 256, 256>>>(W_iou, W_f, U_iou, U_f);

    for (int half = 0; half < 2; half++) {
        dim3 grid(3, HALF_LEAF / 128);
        leaf_gemm<<<grid, 256>>>(x_ids, mask, emb, half * HALF_LEAF);
        leaf_update<<<(HALF_LEAF * HDIM + 255) / 256, 256>>>(half * HALF_LEAF, b_iou);
    }

    for (int d = DEPTH - 2; d >= 0; --d) {
        const int n = 1 << d;
        const int s0 = n - 1;
        dim3 grid(4, (2 * n + 127) / 128);
        level_gemm<<<grid, 256>>>(x_ids, mask, emb, s0, n);
        level_update<<<(n * HDIM + 255) / 256, 256>>>(s0, n, b_iou, b_f);
    }

    out_gemm<<<(NNODES + 7) / 8, 256>>>(W_out, b_out, out);
}

// round 9
// speedup vs baseline: 2.1379x; 1.1737x over previous
#include <cuda_runtime.h>
#include <cuda_bf16.h>
#include <mma.h>
#include <cstdint>
#include <cstddef>

using namespace nvcuda;

#define DEPTH 18
#define NNODES ((1 << DEPTH) - 1)      // 262143
#define HDIM 128
#define LEAF_N (1 << (DEPTH - 1))      // 131072

// ================= device scratch (516 MiB total; largest object 192 MiB) =====
__device__ __align__(128) float g_h[(size_t)NNODES * HDIM];          // 128 MiB
__device__ __align__(128) float g_c[(size_t)NNODES * HDIM];          // 128 MiB
__device__ __align__(128) float g_fraw[(size_t)LEAF_N * HDIM];       // 64 MiB: raw fgate pre-act
__device__ __align__(128) float g_iouraw[(size_t)LEAF_N * 384];      // 192 MiB: raw iou pre-act
// weight images, bf16 pairs packed in uint32: [tile][n(128)][kpair(128)] (K=256)
// tiles 0-2: [W_iou;U_iou] n-tiles, tile 3: [W_f;U_f]
__device__ __align__(128) uint32_t g_Bhi[4 * 128 * 128];
__device__ __align__(128) uint32_t g_Blo[4 * 128 * 128];

__device__ __forceinline__ float sigmf(float x) { return 1.0f / (1.0f + __expf(-x)); }

// pure-integer bf16 hi/lo split (truncation): hi = top16(f), lo = top16(f - hi)
__device__ __forceinline__ void split2(float f0, float f1, uint32_t& hiw, uint32_t& low) {
    const uint32_t h0 = __float_as_uint(f0) & 0xFFFF0000u;
    const uint32_t h1 = __float_as_uint(f1) & 0xFFFF0000u;
    const uint32_t l0 = __float_as_uint(f0 - __uint_as_float(h0)) & 0xFFFF0000u;
    const uint32_t l1 = __float_as_uint(f1 - __uint_as_float(h1)) & 0xFFFF0000u;
    hiw = (h0 >> 16) | h1;
    low = (l0 >> 16) | l1;
}

// ================= static smem layout (bf16 elems, 40-elem padded rows) =====
#define PADK 40
#define E_ALO 5120
#define E_BHI 10240
#define E_BLO 15360
#define SM_ELEMS 20480            // 40 KB

// ================= one-time weight prep =================
// g_B*[t][n][kp]: K rows 0..255 = [W(0..127); U(128..255)], column n (output dim)
__global__ void prep_weights(const float* __restrict__ Wiou, const float* __restrict__ Wf,
                             const float* __restrict__ Uiou, const float* __restrict__ Uf)
{
    const int idx = blockIdx.x * blockDim.x + threadIdx.x;
    if (idx >= 4 * 128 * 128) return;
    const int t = idx >> 14;
    const int n = (idx >> 7) & 127;
    const int kp = idx & 127;
    float v[2];
    #pragma unroll
    for (int e = 0; e < 2; e++) {
        const int k = kp * 2 + e;
        if (t < 3) {
            const int nn = t * 128 + n;
            v[e] = (k < 128) ? Wiou[k * 384 + nn] : Uiou[(k - 128) * 384 + nn];
        } else {
            v[e] = (k < 128) ? Wf[k * 128 + n] : Uf[(k - 128) * 128 + n];
        }
    }
    uint32_t hiw, low;
    split2(v[0], v[1], hiw, low);
    g_Bhi[idx] = hiw;
    g_Blo[idx] = low;
}

// ================= wmma GEMM core =================
// CTA = 128 rows x 128 cols, 8 warps (wm 0..3 = 32 rows, wn 0..1 = 64 cols).
// K chunked by 32; chunk kc<4 sources pe (emb row), kc>=4 sources ph0(+ph1 summed).
// 3 bf16-split products (hi*hi + hi*lo + lo*hi), fp32 accum. Stores raw (no bias).
__device__ __forceinline__ void gemm_core(
    __nv_bfloat16* sm, int tid,
    const float* pe, const float* ph0, const float* ph1,   // per-thread row ptrs (nullable)
    int nkc,
    const uint32_t* bhi, const uint32_t* blo,              // weight tile base (128n x 128kp)
    float* __restrict__ C, int ldC, int m0, int colbase)
{
    const int wid = tid >> 5;
    const int wm = wid >> 1;
    const int wn = wid & 1;
    const int r = tid >> 1;
    const int sel = tid & 1;

    wmma::fragment<wmma::accumulator, 16, 16, 16, float> acc[2][4];
    #pragma unroll
    for (int mt = 0; mt < 2; mt++)
        #pragma unroll
        for (int nt = 0; nt < 4; nt++)
            wmma::fill_fragment(acc[mt][nt], 0.0f);

    for (int kc = 0; kc < nkc; kc++) {
        if (kc) __syncthreads();
        // ---- stage A chunk (2 threads per row, 16 floats each) ----
        {
            const float* p0;
            const float* p1 = nullptr;
            if (kc < 4) {
                p0 = pe ? pe + kc * 32 + sel * 16 : nullptr;
            } else {
                p0 = ph0 ? ph0 + (kc - 4) * 32 + sel * 16 : nullptr;
                p1 = ph1 ? ph1 + (kc - 4) * 32 + sel * 16 : nullptr;
            }
            uint32_t* dhi = (uint32_t*)(sm + r * PADK) + sel * 8;
            uint32_t* dlo = (uint32_t*)(sm + E_ALO + r * PADK) + sel * 8;
            if (p0) {
                #pragma unroll
                for (int q = 0; q < 4; q++) {
                    float4 f = *(const float4*)(p0 + 4 * q);
                    if (p1) {
                        const float4 g = *(const float4*)(p1 + 4 * q);
                        f.x += g.x; f.y += g.y; f.z += g.z; f.w += g.w;
                    }
                    uint32_t h0, l0, h1, l1;
                    split2(f.x, f.y, h0, l0);
                    split2(f.z, f.w, h1, l1);
                    dhi[2 * q] = h0; dhi[2 * q + 1] = h1;
                    dlo[2 * q] = l0; dlo[2 * q + 1] = l1;
                }
            } else {
                #pragma unroll
                for (int q = 0; q < 8; q++) { dhi[q] = 0u; dlo[q] = 0u; }
            }
        }
        // ---- stage B chunk: 128 n-rows x 32 k (4 uint4/row; row = 32 uint4) ----
        {
            const uint4* shi = (const uint4*)bhi + kc * 4;
            const uint4* slo = (const uint4*)blo + kc * 4;
            #pragma unroll
            for (int i = tid; i < 512; i += 256) {
                const int nn = i >> 2;
                const int q = i & 3;
                *(uint4*)(sm + E_BHI + nn * PADK + q * 8) = shi[nn * 32 + q];
                *(uint4*)(sm + E_BLO + nn * PADK + q * 8) = slo[nn * 32 + q];
            }
        }
        __syncthreads();

        #pragma unroll
        for (int p = 0; p < 3; p++) {
            const int aBase = (p == 2) ? E_ALO : 0;
            const int bBase = (p == 1) ? E_BLO : E_BHI;
            #pragma unroll
            for (int ks = 0; ks < 2; ks++) {
                wmma::fragment<wmma::matrix_a, 16, 16, 16, __nv_bfloat16, wmma::row_major> a[2];
                #pragma unroll
                for (int mt = 0; mt < 2; mt++)
                    wmma::load_matrix_sync(a[mt],
                        sm + aBase + (wm * 32 + mt * 16) * PADK + ks * 16, PADK);
                #pragma unroll
                for (int nt = 0; nt < 4; nt++) {
                    wmma::fragment<wmma::matrix_b, 16, 16, 16, __nv_bfloat16, wmma::col_major> b;
                    wmma::load_matrix_sync(b,
                        sm + bBase + (wn * 64 + nt * 16) * PADK + ks * 16, PADK);
                    #pragma unroll
                    for (int mt = 0; mt < 2; mt++)
                        wmma::mma_sync(acc[mt][nt], a[mt], b, acc[mt][nt]);
                }
            }
        }
    }

    #pragma unroll
    for (int mt = 0; mt < 2; mt++)
        #pragma unroll
        for (int nt = 0; nt < 4; nt++) {
            const int row0 = m0 + wm * 32 + mt * 16;
            const int col0 = colbase + wn * 64 + nt * 16;
            wmma::store_matrix_sync(C + (size_t)row0 * ldC + col0, acc[mt][nt],
                                    ldC, wmma::mem_row_major);
        }
}

// leaves: g_iouraw[m] = emb(leaf m) @ W_iou (K=128); grid (3, 1024)
__global__ __launch_bounds__(256, 2)
void leaf_gemm(const int* __restrict__ xids, const int* __restrict__ msk,
               const float* __restrict__ emb)
{
    __shared__ __align__(16) __nv_bfloat16 sm[SM_ELEMS];
    const int tid = threadIdx.x;
    const int bt = blockIdx.x;
    const int m0 = blockIdx.y * 128;

    const int node = (LEAF_N - 1) + m0 + (tid >> 1);
    const int gid = xids[node] * msk[node];
    const float* pe = emb + (size_t)gid * HDIM;

    gemm_core(sm, tid, pe, nullptr, nullptr, 4,
              g_Bhi + bt * 16384, g_Blo + bt * 16384,
              g_iouraw, 384, m0, bt * 128);
}

// internal level: bx 0..2 = iou n-tiles (A=[emb(node)|h_l+h_r], K=256),
//                 bx 3    = fgate      (A=[emb(parent)|h_child], K=256)
__global__ __launch_bounds__(256, 2)
void level_gemm(const int* __restrict__ xids, const int* __restrict__ msk,
                const float* __restrict__ emb, int s0, int n)
{
    __shared__ __align__(16) __nv_bfloat16 sm[SM_ELEMS];
    const int tid = threadIdx.x;
    const int bx = blockIdx.x;
    const int m0 = blockIdx.y * 128;
    const int s1 = 2 * s0 + 1;
    const int r = tid >> 1;

    const float* pe = nullptr;
    const float* ph0 = nullptr;
    const float* ph1 = nullptr;

    if (bx < 3) {
        if (m0 >= n) return;
        const int m = m0 + r;
        if (m < n) {
            const int node = s0 + m;
            const int gid = xids[node] * msk[node];
            pe  = emb + (size_t)gid * HDIM;
            ph0 = g_h + (size_t)(s1 + 2 * m) * HDIM;
            ph1 = g_h + (size_t)(s1 + 2 * m + 1) * HDIM;
        }
        gemm_core(sm, tid, pe, ph0, ph1, 8,
                  g_Bhi + bx * 16384, g_Blo + bx * 16384,
                  g_iouraw, 384, m0, bx * 128);
    } else {
        const int ch = m0 + r;
        if (ch < 2 * n) {
            const int parent = s0 + (ch >> 1);
            const int gid = xids[parent] * msk[parent];
            pe  = emb + (size_t)gid * HDIM;
            ph0 = g_h + (size_t)(s1 + ch) * HDIM;
        }
        gemm_core(sm, tid, pe, ph0, nullptr, 8,
                  g_Bhi + 3 * 16384, g_Blo + 3 * 16384,
                  g_fraw, 128, m0, 0);
    }
}

// ================= elementwise (biases folded here) =================
__global__ void leaf_update(const float* __restrict__ biou)
{
    const int idx = blockIdx.x * blockDim.x + threadIdx.x;
    if (idx >= LEAF_N * HDIM) return;
    const int m = idx >> 7;
    const int j = idx & 127;
    const int node = (LEAF_N - 1) + m;
    const float iv = g_iouraw[(size_t)m * 384 + j]       + biou[j];
    const float ov = g_iouraw[(size_t)m * 384 + 128 + j] + biou[128 + j];
    const float uv = g_iouraw[(size_t)m * 384 + 256 + j] + biou[256 + j];
    const float cv = sigmf(iv) * tanhf(uv);
    const float hv = sigmf(ov) * tanhf(cv);
    g_c[(size_t)node * HDIM + j] = cv;
    g_h[(size_t)node * HDIM + j] = hv;
}

__global__ void level_update(int s0, int n,
                             const float* __restrict__ biou, const float* __restrict__ bfv)
{
    const int idx = blockIdx.x * blockDim.x + threadIdx.x;
    if (idx >= n * HDIM) return;
    const int m = idx >> 7;
    const int j = idx & 127;
    const int node = s0 + m;
    const float bf = bfv[j];
    const float c0 = g_c[(size_t)(2 * node + 1) * HDIM + j];
    const float c1 = g_c[(size_t)(2 * node + 2) * HDIM + j];
    const float f0 = sigmf(g_fraw[(size_t)(2 * m) * HDIM + j] + bf);
    const float f1 = sigmf(g_fraw[(size_t)(2 * m + 1) * HDIM + j] + bf);
    const float fc = f0 * c0 + f1 * c1;
    const float iv = g_iouraw[(size_t)m * 384 + j]       + biou[j];
    const float ov = g_iouraw[(size_t)m * 384 + 128 + j] + biou[128 + j];
    const float uv = g_iouraw[(size_t)m * 384 + 256 + j] + biou[256 + j];
    const float cv = sigmf(iv) * tanhf(uv) + fc;
    const float hv = sigmf(ov) * tanhf(cv);
    g_c[(size_t)node * HDIM + j] = cv;
    g_h[(size_t)node * HDIM + j] = hv;
}

// ================= output projection =================
__global__ void out_gemm(const float* __restrict__ Wout,
                         const float* __restrict__ bout,
                         float* __restrict__ out)
{
    __shared__ float Ws[HDIM * 5];
    __shared__ float bs[5];
    const int tid = threadIdx.x;
    for (int i = tid; i < HDIM * 5; i += blockDim.x) Ws[i] = Wout[i];
    if (tid < 5) bs[tid] = bout[tid];
    __syncthreads();

    const int node = (blockIdx.x * blockDim.x + tid) >> 5;
    const int lane = tid & 31;
    if (node >= NNODES) return;

    const float* hp = g_h + (size_t)node * HDIM;
    float p[5] = {0.f, 0.f, 0.f, 0.f, 0.f};
    #pragma unroll
    for (int e = 0; e < 4; e++) {
        const int k = e * 32 + lane;
        const float x = hp[k];
        #pragma unroll
        for (int c = 0; c < 5; c++) p[c] += x * Ws[k * 5 + c];
    }
    #pragma unroll
    for (int off = 16; off > 0; off >>= 1)
        #pragma unroll
        for (int c = 0; c < 5; c++)
            p[c] += __shfl_xor_sync(0xffffffffu, p[c], off);

    if (lane == 0) {
        #pragma unroll
        for (int c = 0; c < 5; c++)
            out[(size_t)node * 5 + c] = p[c] + bs[c];
    }
}

// ================= launch =================
extern "C" void kernel_launch(void* const* d_in, const int* in_sizes, int n_in,
                              void* d_out, int out_size)
{
    const int*   x_ids = (const int*)d_in[0];
    const int*   mask  = (const int*)d_in[1];
    const float* emb   = (const float*)d_in[2];
    const float* W_iou = (const float*)d_in[3];
    const float* U_iou = (const float*)d_in[4];
    const float* b_iou = (const float*)d_in[5];
    const float* W_f   = (const float*)d_in[6];
    const float* U_f   = (const float*)d_in[7];
    const float* b_f   = (const float*)d_in[8];
    const float* W_out = (const float*)d_in[9];
    const float* b_out = (const float*)d_in[10];
    float* out = (float*)d_out;

    prep_weights<<<(4 * 128 * 128 + 255) / 256, 256>>>(W_iou, W_f, U_iou, U_f);

    {
        dim3 grid(3, LEAF_N / 128);
        leaf_gemm<<<grid, 256>>>(x_ids, mask, emb);
        leaf_update<<<(LEAF_N * HDIM + 255) / 256, 256>>>(b_iou);
    }

    for (int d = DEPTH - 2; d >= 0; --d) {
        const int n = 1 << d;
        const int s0 = n - 1;
        dim3 grid(4, (2 * n + 127) / 128);
        level_gemm<<<grid, 256>>>(x_ids, mask, emb, s0, n);
        level_update<<<(n * HDIM + 255) / 256, 256>>>(s0, n, b_iou, b_f);
    }

    out_gemm<<<(NNODES + 7) / 8, 256>>>(W_out, b_out, out);
}